// round 12
// baseline (speedup 1.0000x reference)
#include <cuda_runtime.h>
#include <cuda.h>
#include <cuda_fp16.h>
#include <cstdint>
#include <math.h>

// q[n][p] = softmax_p( <emb_n/|emb_n|, c_p/|c_p|> / T ), no max-subtraction.
// Round 12 EXPERIMENT: f16-accumulate HMMA rate test. Evidence says f32-acc
// mma.sync is pinned at ~512 MAC/cyc/SM (HW issue ceiling) across all configs.
// f16-acc variant may be 2x. Chains fp16 accumulation only within one K=64
// chunk (4 HMMAs), promotes to fp32 per chunk: adds ~3.5e-4 error, under gate.
// Base: R11 (128x128 tile, 16 consumer warps of 32x32, 2 CTAs/SM).

#define D_DIM 768
#define TM 128
#define TN 128
#define KC 64                        // K halves per chunk (128B rows, SW128)
#define NCH (D_DIM / KC)             // 12
#define PIPE 3
#define A_ST (TM * KC * 2)           // 16384 B
#define B_ST (TN * KC * 2)           // 16384 B
#define SMEM_A_OFF 1024
#define SMEM_B_OFF (SMEM_A_OFF + PIPE * A_ST)
#define SMEM_TOTAL (SMEM_B_OFF + PIPE * B_ST)   // 99328 B -> 2 CTAs/SM

#define OFF_FULL  0                  // 3 x 8B
#define OFF_EMPTY 32                 // 3 x 8B
#define OFF_FLAG  64                 // 4B
#define OFF_SINV  128                // 128 x 4B

#define MAXN 65536
#define MAXP 4096
#define MAXSTRIPES (MAXN / TM)
__device__ __half g_a16[(size_t)MAXN * D_DIM];   // normalized emb, fp16
__device__ __half g_b16[(size_t)MAXP * D_DIM];   // normalized prototypes, fp16
__device__ float g_rowsum[MAXN];
__device__ int g_cnt[MAXSTRIPES];

// ---------------------------------------------------------------------------
// PTX helpers
// ---------------------------------------------------------------------------
__device__ __forceinline__ uint32_t smem_u32(const void* p) {
    uint32_t a;
    asm("{ .reg .u64 t; cvta.to.shared.u64 t, %1; cvt.u32.u64 %0, t; }" : "=r"(a) : "l"(p));
    return a;
}
__device__ __forceinline__ void mbar_init(uint32_t bar, uint32_t cnt) {
    asm volatile("mbarrier.init.shared.b64 [%0], %1;" :: "r"(bar), "r"(cnt) : "memory");
}
__device__ __forceinline__ void mbar_expect_tx(uint32_t bar, uint32_t bytes) {
    asm volatile("mbarrier.arrive.expect_tx.shared.b64 _, [%0], %1;" :: "r"(bar), "r"(bytes) : "memory");
}
__device__ __forceinline__ void mbar_arrive(uint32_t bar) {
    asm volatile("mbarrier.arrive.shared.b64 _, [%0];" :: "r"(bar) : "memory");
}
__device__ __forceinline__ void mbar_wait(uint32_t bar, uint32_t parity) {
    uint32_t done;
    asm volatile(
        "{ .reg .pred p; mbarrier.try_wait.parity.acquire.cta.shared::cta.b64 p, [%1], %2;"
        " selp.b32 %0, 1, 0, p; }" : "=r"(done) : "r"(bar), "r"(parity) : "memory");
    if (!done) {
        asm volatile(
            "{ .reg .pred P1; WL%=:"
            " mbarrier.try_wait.parity.acquire.cta.shared::cta.b64 P1, [%0], %1, 0x989680;"
            " @P1 bra.uni WD%=; bra.uni WL%=; WD%=: }"
            :: "r"(bar), "r"(parity) : "memory");
    }
}
__device__ __forceinline__ void tma2d(uint32_t dst, const void* map, int x, int y, uint32_t bar) {
    asm volatile(
        "cp.async.bulk.tensor.2d.shared::cta.global.tile.mbarrier::complete_tx::bytes "
        "[%0], [%1, {%2, %3}], [%4];"
        :: "r"(dst), "l"(map), "r"(x), "r"(y), "r"(bar) : "memory");
}
__device__ __forceinline__ void ldsm4(uint32_t* r, uint32_t addr) {
    asm volatile("ldmatrix.sync.aligned.m8n8.x4.shared.b16 {%0,%1,%2,%3}, [%4];"
                 : "=r"(r[0]), "=r"(r[1]), "=r"(r[2]), "=r"(r[3]) : "r"(addr));
}
// f16-accumulate HMMA: D,C are 2 regs (4 halves). Chain within one chunk only.
__device__ __forceinline__ void mma_f16h(uint32_t* d, const uint32_t* a, uint32_t b0, uint32_t b1) {
    asm volatile(
        "mma.sync.aligned.m16n8k16.row.col.f16.f16.f16.f16 "
        "{%0,%1}, {%2,%3,%4,%5}, {%6,%7}, {%0,%1};"
        : "+r"(d[0]), "+r"(d[1])
        : "r"(a[0]), "r"(a[1]), "r"(a[2]), "r"(a[3]), "r"(b0), "r"(b1));
}
__device__ __forceinline__ float ex2(float x) {
    float y;
    asm("ex2.approx.ftz.f32 %0, %1;" : "=f"(y) : "f"(x));
    return y;
}
__device__ __forceinline__ void barc() {   // consumer-only named barrier (512 thr)
    asm volatile("bar.sync 1, 512;" ::: "memory");
}

// ---------------------------------------------------------------------------
// Kernel 1: warp-per-row: fp32 L2 norm -> normalized fp16 row.
// Also zeroes g_rowsum and g_cnt.
// ---------------------------------------------------------------------------
__global__ void conv_kernel(const float* __restrict__ A, const float* __restrict__ B,
                            int N, int P) {
    int gtid = blockIdx.x * blockDim.x + threadIdx.x;
    if (gtid < MAXSTRIPES) g_cnt[gtid] = 0;
    int w = gtid >> 5;
    int lane = threadIdx.x & 31;
    if (w >= N + P) return;
    const float4* src;
    __half2* dst;
    if (w < N) {
        src = (const float4*)(A + (size_t)w * D_DIM);
        dst = (__half2*)(g_a16 + (size_t)w * D_DIM);
        if (lane == 0) g_rowsum[w] = 0.0f;
    } else {
        int r = w - N;
        src = (const float4*)(B + (size_t)r * D_DIM);
        dst = (__half2*)(g_b16 + (size_t)r * D_DIM);
    }
    float4 v[D_DIM / 128];
    float ss = 0.0f;
#pragma unroll
    for (int i = 0; i < D_DIM / 128; i++) {
        v[i] = src[lane + 32 * i];
        ss += v[i].x * v[i].x + v[i].y * v[i].y + v[i].z * v[i].z + v[i].w * v[i].w;
    }
#pragma unroll
    for (int o = 16; o; o >>= 1) ss += __shfl_xor_sync(0xffffffffu, ss, o);
    float inv = 1.0f / fmaxf(sqrtf(ss), 1e-12f);
#pragma unroll
    for (int i = 0; i < D_DIM / 128; i++) {
        dst[(lane + 32 * i) * 2]     = __floats2half2_rn(v[i].x * inv, v[i].y * inv);
        dst[(lane + 32 * i) * 2 + 1] = __floats2half2_rn(v[i].z * inv, v[i].w * inv);
    }
}

// ---------------------------------------------------------------------------
// Kernel 2: one CTA per 128x128 tile. 16 consumer warps (4x4 grid, 32x32 warp
// tile, f16-acc chains per chunk + fp32 promote) + 1 TMA producer. 2 CTAs/SM.
// ---------------------------------------------------------------------------
__global__ void __launch_bounds__(544, 2)
gemm_kernel(const __grid_constant__ CUtensorMap tmap_a,
            const __grid_constant__ CUtensorMap tmap_b,
            const float* __restrict__ tptr,
            float* __restrict__ out,
            int N, int P) {
    extern __shared__ char smem[];
    uint32_t sbase = smem_u32(smem);
    const int tid = threadIdx.x, wid = tid >> 5, lane = tid & 31;
    const int ntp = P / TN;                       // 32
    const int stripe = blockIdx.x / ntp;
    const int n0 = stripe * TM;
    const int p0 = (blockIdx.x % ntp) * TN;
    int* sflag = (int*)(smem + OFF_FLAG);
    float* sinv = (float*)(smem + OFF_SINV);

    if (tid == 0) {
#pragma unroll
        for (int s = 0; s < PIPE; s++) {
            mbar_init(sbase + OFF_FULL + s * 8, 1);
            mbar_init(sbase + OFF_EMPTY + s * 8, 16);   // 16 consumer warps
        }
    }
    __syncthreads();
    asm volatile("fence.proxy.async.shared::cta;" ::: "memory");

    if (wid == 16) {
        if (lane == 0) {
            int st = 0, ph = 1;
            for (int c = 0; c < NCH; c++) {
                mbar_wait(sbase + OFF_EMPTY + st * 8, ph);
                mbar_expect_tx(sbase + OFF_FULL + st * 8, A_ST + B_ST);
                tma2d(sbase + SMEM_A_OFF + st * A_ST, &tmap_a, c * KC, n0,
                      sbase + OFF_FULL + st * 8);
                tma2d(sbase + SMEM_B_OFF + st * B_ST, &tmap_b, c * KC, p0,
                      sbase + OFF_FULL + st * 8);
                if (++st == PIPE) { st = 0; ph ^= 1; }
            }
        }
        return;
    }

    // consumers: warp (wm, wn) in 4x4 grid owns 32x32 subtile
    const int wm = wid >> 2;                      // 0..3
    const int wn = wid & 3;                       // 0..3
    const int lrow = lane & 15;
    const uint32_t lgrp = (uint32_t)((lane >> 4) * 16);
    const uint32_t kb0 = (uint32_t)((wid & 3) * 32);   // staggered k16 start

    uint32_t arow[2], asw[2], brow[2], bsw[2];
#pragma unroll
    for (int mt = 0; mt < 2; mt++) {
        uint32_t r = (uint32_t)(wm * 32 + mt * 16 + lrow);
        arow[mt] = r * 128;
        asw[mt] = (r & 7) << 4;
    }
#pragma unroll
    for (int bt = 0; bt < 2; bt++) {
        uint32_t r = (uint32_t)(wn * 32 + bt * 16 + lrow);
        brow[bt] = r * 128;
        bsw[bt] = (r & 7) << 4;
    }

    float acc[2][4][4];                 // fp32 master accumulators
#pragma unroll
    for (int mt = 0; mt < 2; mt++)
#pragma unroll
        for (int nt = 0; nt < 4; nt++)
#pragma unroll
            for (int q = 0; q < 4; q++) acc[mt][nt][q] = 0.0f;

#pragma unroll
    for (int c = 0; c < NCH; c++) {
        const int st = c % PIPE;                 // compile-time
        const uint32_t wph = (c / PIPE) & 1;     // compile-time
        // fresh fp16 chain per chunk
        uint32_t hacc[2][4][2];
#pragma unroll
        for (int mt = 0; mt < 2; mt++)
#pragma unroll
            for (int nt = 0; nt < 4; nt++) {
                hacc[mt][nt][0] = 0u;
                hacc[mt][nt][1] = 0u;
            }
        mbar_wait(sbase + OFF_FULL + st * 8, wph);
        const uint32_t abase = sbase + SMEM_A_OFF + st * A_ST;
        const uint32_t bbase = sbase + SMEM_B_OFF + st * B_ST;
#pragma unroll
        for (int ks = 0; ks < 4; ks++) {
            const uint32_t kin = ((kb0 + ks * 32) & 96) | lgrp;
            uint32_t b[2][4];
#pragma unroll
            for (int bt = 0; bt < 2; bt++)
                ldsm4(b[bt], bbase + brow[bt] + (kin ^ bsw[bt]));
            uint32_t a0[4];
            ldsm4(a0, abase + arow[0] + (kin ^ asw[0]));
#pragma unroll
            for (int nt = 0; nt < 4; nt++)
                mma_f16h(hacc[0][nt], a0, b[nt >> 1][nt & 1], b[nt >> 1][2 + (nt & 1)]);
            uint32_t a1[4];
            ldsm4(a1, abase + arow[1] + (kin ^ asw[1]));
            if (ks == 3 && lane == 0) mbar_arrive(sbase + OFF_EMPTY + st * 8);
#pragma unroll
            for (int nt = 0; nt < 4; nt++)
                mma_f16h(hacc[1][nt], a1, b[nt >> 1][nt & 1], b[nt >> 1][2 + (nt & 1)]);
        }
        // promote chunk's fp16 partials into fp32 accumulators
#pragma unroll
        for (int mt = 0; mt < 2; mt++)
#pragma unroll
            for (int nt = 0; nt < 4; nt++) {
                float2 f0 = __half22float2(*(__half2*)&hacc[mt][nt][0]);
                float2 f1 = __half22float2(*(__half2*)&hacc[mt][nt][1]);
                acc[mt][nt][0] += f0.x;
                acc[mt][nt][1] += f0.y;
                acc[mt][nt][2] += f1.x;
                acc[mt][nt][3] += f1.y;
            }
    }

    // epilogue: e = exp2(acc * log2(e)/T) -> out; rowsum atomics
    const float s = 1.4426950408889634f / tptr[0];
    const int qrow = lane >> 2;
    const int qc = 2 * (lane & 3);
#pragma unroll
    for (int mt = 0; mt < 2; mt++) {
#pragma unroll
        for (int h = 0; h < 2; h++) {
            int row = n0 + wm * 32 + mt * 16 + h * 8 + qrow;
            float rs = 0.0f;
            float* orow = out + (size_t)row * P + p0 + wn * 32 + qc;
#pragma unroll
            for (int nt = 0; nt < 4; nt++) {
                float e0 = ex2(acc[mt][nt][2 * h] * s);
                float e1 = ex2(acc[mt][nt][2 * h + 1] * s);
                rs += e0 + e1;
                *(float2*)(orow + nt * 8) = make_float2(e0, e1);
            }
            rs += __shfl_xor_sync(0xffffffffu, rs, 1);
            rs += __shfl_xor_sync(0xffffffffu, rs, 2);
            if ((lane & 3) == 0) atomicAdd(&g_rowsum[row], rs);
        }
    }

    // ---- last-CTA-of-stripe scales the stripe in place ----
    __threadfence();
    barc();
    if (tid == 0) {
        int old = atomicAdd(&g_cnt[stripe], 1);
        sflag[0] = (old == ntp - 1);
    }
    barc();
    if (sflag[0]) {
        if (tid < TM) sinv[tid] = 1.0f / g_rowsum[n0 + tid];
        barc();
        const int p4 = P >> 2;
        float4* base = (float4*)(out + (size_t)n0 * P);
        for (int r = 0; r < TM; r++) {
            float inv = sinv[r];
            float4* rowp = base + r * p4;
#pragma unroll 2
            for (int c4 = tid; c4 < p4; c4 += 512) {
                float4 v = rowp[c4];
                v.x *= inv; v.y *= inv; v.z *= inv; v.w *= inv;
                rowp[c4] = v;
            }
        }
    }
}

// ---------------------------------------------------------------------------
extern "C" void kernel_launch(void* const* d_in, const int* in_sizes, int n_in,
                              void* d_out, int out_size) {
    const float* emb = (const float*)d_in[0];
    const float* proto = (const float*)d_in[1];
    const float* temp = (const float*)d_in[2];
    float* out = (float*)d_out;
    const int N = in_sizes[0] / D_DIM;
    const int P = in_sizes[1] / D_DIM;

    typedef CUresult (*EncodeFn)(CUtensorMap*, CUtensorMapDataType, cuuint32_t, void*,
                                 const cuuint64_t*, const cuuint64_t*, const cuuint32_t*,
                                 const cuuint32_t*, CUtensorMapInterleave, CUtensorMapSwizzle,
                                 CUtensorMapL2promotion, CUtensorMapFloatOOBfill);
    EncodeFn encode = nullptr;
    cudaDriverEntryPointQueryResult qr;
    cudaGetDriverEntryPoint("cuTensorMapEncodeTiled", (void**)&encode,
                            cudaEnableDefault, &qr);

    void *pa = nullptr, *pb = nullptr;
    cudaGetSymbolAddress(&pa, g_a16);
    cudaGetSymbolAddress(&pb, g_b16);

    CUtensorMap tma_a{}, tma_b{};
    {
        cuuint64_t dims[2] = {(cuuint64_t)D_DIM, (cuuint64_t)N};
        cuuint64_t strides[1] = {(cuuint64_t)D_DIM * 2};
        cuuint32_t box[2] = {KC, TM};
        cuuint32_t es[2] = {1, 1};
        encode(&tma_a, CU_TENSOR_MAP_DATA_TYPE_FLOAT16, 2, pa, dims, strides, box, es,
               CU_TENSOR_MAP_INTERLEAVE_NONE, CU_TENSOR_MAP_SWIZZLE_128B,
               CU_TENSOR_MAP_L2_PROMOTION_L2_128B, CU_TENSOR_MAP_FLOAT_OOB_FILL_NONE);
    }
    {
        cuuint64_t dims[2] = {(cuuint64_t)D_DIM, (cuuint64_t)P};
        cuuint64_t strides[1] = {(cuuint64_t)D_DIM * 2};
        cuuint32_t box[2] = {KC, TN};
        cuuint32_t es[2] = {1, 1};
        encode(&tma_b, CU_TENSOR_MAP_DATA_TYPE_FLOAT16, 2, pb, dims, strides, box, es,
               CU_TENSOR_MAP_INTERLEAVE_NONE, CU_TENSOR_MAP_SWIZZLE_128B,
               CU_TENSOR_MAP_L2_PROMOTION_L2_128B, CU_TENSOR_MAP_FLOAT_OOB_FILL_NONE);
    }

    // 1) normalize + fp16 convert + rowsum/counter zeroing
    int rows = N + P;
    conv_kernel<<<(rows * 32 + 255) / 256, 256>>>(emb, proto, N, P);

    // 2) fused GEMM + softmax (f16-acc chains + per-chunk fp32 promote)
    int NT = (N / TM) * (P / TN);
    cudaFuncSetAttribute(gemm_kernel, cudaFuncAttributeMaxDynamicSharedMemorySize, SMEM_TOTAL);
    gemm_kernel<<<NT, 544, SMEM_TOTAL>>>(tma_a, tma_b, temp, out, N, P);
}

// round 13
// speedup vs baseline: 1.7429x; 1.7429x over previous
#include <cuda_runtime.h>
#include <cuda.h>
#include <cuda_fp16.h>
#include <cstdint>
#include <math.h>

// q[n][p] = softmax_p( <emb_n/|emb_n|, c_p/|c_p|> / T ), no max-subtraction.
// Round 13: persistent-CTA version of the proven R8 config (128x128 tile,
// 8 consumer warps of 32x64, f32-acc HMMA, PIPE=3, 2 CTAs/SM). Each CTA loops
// over tiles via a global ticket; the TMA producer free-runs across tile
// boundaries so the ring never drains (epilogue of tile k overlaps prefetch
// of tile k+1; per-tile pipeline fill eliminated). 12 chunks % PIPE==0 makes
// the unrolled compile-time stage/parity pattern repeat every tile.

#define D_DIM 768
#define TM 128
#define TN 128
#define KC 64                        // K halves per chunk (128B rows, SW128)
#define NCH (D_DIM / KC)             // 12
#define PIPE 3
#define A_ST (TM * KC * 2)           // 16384 B
#define B_ST (TN * KC * 2)           // 16384 B
#define SMEM_A_OFF 1024
#define SMEM_B_OFF (SMEM_A_OFF + PIPE * A_ST)
#define SMEM_TOTAL (SMEM_B_OFF + PIPE * B_ST)   // 99328 B -> 2 CTAs/SM

#define OFF_FULL  0                  // 3 x 8B
#define OFF_EMPTY 32                 // 3 x 8B
#define OFF_SFULL 64                 // 8B: tile-id handoff barrier
#define OFF_SID   80                 // 2 x 4B: double-buffered tile id
#define OFF_FLAG  96                 // 4B
#define OFF_SINV  128                // 128 x 4B

#define MAXN 65536
#define MAXP 4096
#define MAXSTRIPES (MAXN / TM)
__device__ __half g_a16[(size_t)MAXN * D_DIM];   // normalized emb, fp16
__device__ __half g_b16[(size_t)MAXP * D_DIM];   // normalized prototypes, fp16
__device__ float g_rowsum[MAXN];
__device__ int g_cnt[MAXSTRIPES];
__device__ int g_ticket;

// ---------------------------------------------------------------------------
// PTX helpers
// ---------------------------------------------------------------------------
__device__ __forceinline__ uint32_t smem_u32(const void* p) {
    uint32_t a;
    asm("{ .reg .u64 t; cvta.to.shared.u64 t, %1; cvt.u32.u64 %0, t; }" : "=r"(a) : "l"(p));
    return a;
}
__device__ __forceinline__ void mbar_init(uint32_t bar, uint32_t cnt) {
    asm volatile("mbarrier.init.shared.b64 [%0], %1;" :: "r"(bar), "r"(cnt) : "memory");
}
__device__ __forceinline__ void mbar_expect_tx(uint32_t bar, uint32_t bytes) {
    asm volatile("mbarrier.arrive.expect_tx.shared.b64 _, [%0], %1;" :: "r"(bar), "r"(bytes) : "memory");
}
__device__ __forceinline__ void mbar_arrive(uint32_t bar) {
    asm volatile("mbarrier.arrive.shared.b64 _, [%0];" :: "r"(bar) : "memory");
}
__device__ __forceinline__ void mbar_wait(uint32_t bar, uint32_t parity) {
    uint32_t done;
    asm volatile(
        "{ .reg .pred p; mbarrier.try_wait.parity.acquire.cta.shared::cta.b64 p, [%1], %2;"
        " selp.b32 %0, 1, 0, p; }" : "=r"(done) : "r"(bar), "r"(parity) : "memory");
    if (!done) {
        asm volatile(
            "{ .reg .pred P1; WL%=:"
            " mbarrier.try_wait.parity.acquire.cta.shared::cta.b64 P1, [%0], %1, 0x989680;"
            " @P1 bra.uni WD%=; bra.uni WL%=; WD%=: }"
            :: "r"(bar), "r"(parity) : "memory");
    }
}
__device__ __forceinline__ void tma2d(uint32_t dst, const void* map, int x, int y, uint32_t bar) {
    asm volatile(
        "cp.async.bulk.tensor.2d.shared::cta.global.tile.mbarrier::complete_tx::bytes "
        "[%0], [%1, {%2, %3}], [%4];"
        :: "r"(dst), "l"(map), "r"(x), "r"(y), "r"(bar) : "memory");
}
__device__ __forceinline__ void ldsm4(uint32_t* r, uint32_t addr) {
    asm volatile("ldmatrix.sync.aligned.m8n8.x4.shared.b16 {%0,%1,%2,%3}, [%4];"
                 : "=r"(r[0]), "=r"(r[1]), "=r"(r[2]), "=r"(r[3]) : "r"(addr));
}
__device__ __forceinline__ void mma_f16(float* d, const uint32_t* a, uint32_t b0, uint32_t b1) {
    asm volatile(
        "mma.sync.aligned.m16n8k16.row.col.f32.f16.f16.f32 "
        "{%0,%1,%2,%3}, {%4,%5,%6,%7}, {%8,%9}, {%0,%1,%2,%3};"
        : "+f"(d[0]), "+f"(d[1]), "+f"(d[2]), "+f"(d[3])
        : "r"(a[0]), "r"(a[1]), "r"(a[2]), "r"(a[3]), "r"(b0), "r"(b1));
}
__device__ __forceinline__ float ex2(float x) {
    float y;
    asm("ex2.approx.ftz.f32 %0, %1;" : "=f"(y) : "f"(x));
    return y;
}
__device__ __forceinline__ void barc() {   // consumer-only named barrier (256 thr)
    asm volatile("bar.sync 1, 256;" ::: "memory");
}

// ---------------------------------------------------------------------------
// Kernel 1: warp-per-row: fp32 L2 norm -> normalized fp16 row.
// Also zeroes g_rowsum, g_cnt, g_ticket.
// ---------------------------------------------------------------------------
__global__ void conv_kernel(const float* __restrict__ A, const float* __restrict__ B,
                            int N, int P) {
    int gtid = blockIdx.x * blockDim.x + threadIdx.x;
    if (gtid < MAXSTRIPES) g_cnt[gtid] = 0;
    if (gtid == 0) g_ticket = 0;
    int w = gtid >> 5;
    int lane = threadIdx.x & 31;
    if (w >= N + P) return;
    const float4* src;
    __half2* dst;
    if (w < N) {
        src = (const float4*)(A + (size_t)w * D_DIM);
        dst = (__half2*)(g_a16 + (size_t)w * D_DIM);
        if (lane == 0) g_rowsum[w] = 0.0f;
    } else {
        int r = w - N;
        src = (const float4*)(B + (size_t)r * D_DIM);
        dst = (__half2*)(g_b16 + (size_t)r * D_DIM);
    }
    float4 v[D_DIM / 128];
    float ss = 0.0f;
#pragma unroll
    for (int i = 0; i < D_DIM / 128; i++) {
        v[i] = src[lane + 32 * i];
        ss += v[i].x * v[i].x + v[i].y * v[i].y + v[i].z * v[i].z + v[i].w * v[i].w;
    }
#pragma unroll
    for (int o = 16; o; o >>= 1) ss += __shfl_xor_sync(0xffffffffu, ss, o);
    float inv = 1.0f / fmaxf(sqrtf(ss), 1e-12f);
#pragma unroll
    for (int i = 0; i < D_DIM / 128; i++) {
        dst[(lane + 32 * i) * 2]     = __floats2half2_rn(v[i].x * inv, v[i].y * inv);
        dst[(lane + 32 * i) * 2 + 1] = __floats2half2_rn(v[i].z * inv, v[i].w * inv);
    }
}

// ---------------------------------------------------------------------------
// Kernel 2: persistent. Each CTA loops over 128x128 tiles (global ticket).
// 8 consumer warps (32x64) + 1 free-running TMA producer warp. 2 CTAs/SM.
// ---------------------------------------------------------------------------
__global__ void __launch_bounds__(288, 2)
gemm_kernel(const __grid_constant__ CUtensorMap tmap_a,
            const __grid_constant__ CUtensorMap tmap_b,
            const float* __restrict__ tptr,
            float* __restrict__ out,
            int N, int P) {
    extern __shared__ char smem[];
    uint32_t sbase = smem_u32(smem);
    const int tid = threadIdx.x, wid = tid >> 5, lane = tid & 31;
    const int ntp = P / TN;                       // 32
    const int NT = (N / TM) * ntp;                // 16384
    int* sflag = (int*)(smem + OFF_FLAG);
    float* sinv = (float*)(smem + OFF_SINV);
    volatile int* sid = (volatile int*)(smem + OFF_SID);

    if (tid == 0) {
#pragma unroll
        for (int s = 0; s < PIPE; s++) {
            mbar_init(sbase + OFF_FULL + s * 8, 1);
            mbar_init(sbase + OFF_EMPTY + s * 8, 8);
        }
        mbar_init(sbase + OFF_SFULL, 1);
    }
    __syncthreads();
    asm volatile("fence.proxy.async.shared::cta;" ::: "memory");

    if (wid == 8) {
        // ---- free-running TMA producer: streams chunks across tiles ----
        if (lane == 0) {
            int sp = 0;
            for (;;) {
                int t = atomicAdd(&g_ticket, 1);
                sid[sp] = t;
                mbar_arrive(sbase + OFF_SFULL);
                sp ^= 1;
                if (t >= NT) break;
                const int n0 = (t / ntp) * TM;
                const int p0 = (t % ntp) * TN;
                // 12 chunks % PIPE == 0 -> same stage/parity pattern each tile
#pragma unroll
                for (int c = 0; c < NCH; c++) {
                    const int st = c % PIPE;
                    const uint32_t eph = 1u ^ ((c / PIPE) & 1);
                    mbar_wait(sbase + OFF_EMPTY + st * 8, eph);
                    mbar_expect_tx(sbase + OFF_FULL + st * 8, A_ST + B_ST);
                    tma2d(sbase + SMEM_A_OFF + st * A_ST, &tmap_a, c * KC, n0,
                          sbase + OFF_FULL + st * 8);
                    tma2d(sbase + SMEM_B_OFF + st * B_ST, &tmap_b, c * KC, p0,
                          sbase + OFF_FULL + st * 8);
                }
            }
        }
        return;
    }

    // consumers: warp (wm, wn) owns 32x64 subtile
    const int wm = wid >> 1;
    const int wn = wid & 1;
    const int lrow = lane & 15;
    const uint32_t lgrp = (uint32_t)((lane >> 4) * 16);
    const uint32_t kb0 = (uint32_t)((wid & 3) * 32);   // staggered k16 start

    uint32_t arow[2], asw[2], brow[4], bsw[4];
#pragma unroll
    for (int mt = 0; mt < 2; mt++) {
        uint32_t r = (uint32_t)(wm * 32 + mt * 16 + lrow);
        arow[mt] = r * 128;
        asw[mt] = (r & 7) << 4;
    }
#pragma unroll
    for (int bt = 0; bt < 4; bt++) {
        uint32_t r = (uint32_t)(wn * 64 + bt * 16 + lrow);
        brow[bt] = r * 128;
        bsw[bt] = (r & 7) << 4;
    }

    const float s = 1.4426950408889634f / tptr[0];
    const int qrow = lane >> 2;
    const int qc = 2 * (lane & 3);

    int phc = 0;
    for (;;) {
        mbar_wait(sbase + OFF_SFULL, phc);
        int t = sid[phc & 1];
        phc ^= 1;
        if (t >= NT) break;
        const int stripe = t / ntp;
        const int n0 = stripe * TM;
        const int p0 = (t % ntp) * TN;

        float acc[2][8][4];
#pragma unroll
        for (int mt = 0; mt < 2; mt++)
#pragma unroll
            for (int nt = 0; nt < 8; nt++)
#pragma unroll
                for (int q = 0; q < 4; q++) acc[mt][nt][q] = 0.0f;

#pragma unroll
        for (int c = 0; c < NCH; c++) {
            const int st = c % PIPE;                 // compile-time
            const uint32_t wph = (c / PIPE) & 1;     // compile-time
            mbar_wait(sbase + OFF_FULL + st * 8, wph);
            const uint32_t abase = sbase + SMEM_A_OFF + st * A_ST;
            const uint32_t bbase = sbase + SMEM_B_OFF + st * B_ST;
#pragma unroll
            for (int ks = 0; ks < 4; ks++) {
                const uint32_t kin = ((kb0 + ks * 32) & 96) | lgrp;
                uint32_t a[2][4];
#pragma unroll
                for (int mt = 0; mt < 2; mt++)
                    ldsm4(a[mt], abase + arow[mt] + (kin ^ asw[mt]));
                uint32_t b[4][4];
#pragma unroll
                for (int bt = 0; bt < 4; bt++)
                    ldsm4(b[bt], bbase + brow[bt] + (kin ^ bsw[bt]));
                if (ks == 3 && lane == 0) mbar_arrive(sbase + OFF_EMPTY + st * 8);
#pragma unroll
                for (int mt = 0; mt < 2; mt++)
#pragma unroll
                    for (int nt = 0; nt < 8; nt++)
                        mma_f16(acc[mt][nt], a[mt],
                                b[nt >> 1][nt & 1], b[nt >> 1][2 + (nt & 1)]);
            }
        }

        // epilogue: e = exp2(acc * log2(e)/T) -> out; rowsum atomics
#pragma unroll
        for (int mt = 0; mt < 2; mt++) {
#pragma unroll
            for (int h = 0; h < 2; h++) {
                int row = n0 + wm * 32 + mt * 16 + h * 8 + qrow;
                float rs = 0.0f;
                float* orow = out + (size_t)row * P + p0 + wn * 64 + qc;
#pragma unroll
                for (int nt = 0; nt < 8; nt++) {
                    float e0 = ex2(acc[mt][nt][2 * h] * s);
                    float e1 = ex2(acc[mt][nt][2 * h + 1] * s);
                    rs += e0 + e1;
                    *(float2*)(orow + nt * 8) = make_float2(e0, e1);
                }
                rs += __shfl_xor_sync(0xffffffffu, rs, 1);
                rs += __shfl_xor_sync(0xffffffffu, rs, 2);
                if ((lane & 3) == 0) atomicAdd(&g_rowsum[row], rs);
            }
        }

        // ---- last-CTA-of-stripe scales the stripe in place ----
        __threadfence();
        barc();
        if (tid == 0) {
            int old = atomicAdd(&g_cnt[stripe], 1);
            sflag[0] = (old == ntp - 1);
        }
        barc();
        if (sflag[0]) {
            if (tid < TM) sinv[tid] = 1.0f / g_rowsum[n0 + tid];
            barc();
            const int p4 = P >> 2;
            float4* base = (float4*)(out + (size_t)n0 * P);
            for (int r = 0; r < TM; r++) {
                float inv = sinv[r];
                float4* rowp = base + r * p4;
#pragma unroll 2
                for (int c4 = tid; c4 < p4; c4 += 256) {
                    float4 v = rowp[c4];
                    v.x *= inv; v.y *= inv; v.z *= inv; v.w *= inv;
                    rowp[c4] = v;
                }
            }
        }
    }
}

// ---------------------------------------------------------------------------
extern "C" void kernel_launch(void* const* d_in, const int* in_sizes, int n_in,
                              void* d_out, int out_size) {
    const float* emb = (const float*)d_in[0];
    const float* proto = (const float*)d_in[1];
    const float* temp = (const float*)d_in[2];
    float* out = (float*)d_out;
    const int N = in_sizes[0] / D_DIM;
    const int P = in_sizes[1] / D_DIM;

    typedef CUresult (*EncodeFn)(CUtensorMap*, CUtensorMapDataType, cuuint32_t, void*,
                                 const cuuint64_t*, const cuuint64_t*, const cuuint32_t*,
                                 const cuuint32_t*, CUtensorMapInterleave, CUtensorMapSwizzle,
                                 CUtensorMapL2promotion, CUtensorMapFloatOOBfill);
    EncodeFn encode = nullptr;
    cudaDriverEntryPointQueryResult qr;
    cudaGetDriverEntryPoint("cuTensorMapEncodeTiled", (void**)&encode,
                            cudaEnableDefault, &qr);

    void *pa = nullptr, *pb = nullptr;
    cudaGetSymbolAddress(&pa, g_a16);
    cudaGetSymbolAddress(&pb, g_b16);

    CUtensorMap tma_a{}, tma_b{};
    {
        cuuint64_t dims[2] = {(cuuint64_t)D_DIM, (cuuint64_t)N};
        cuuint64_t strides[1] = {(cuuint64_t)D_DIM * 2};
        cuuint32_t box[2] = {KC, TM};
        cuuint32_t es[2] = {1, 1};
        encode(&tma_a, CU_TENSOR_MAP_DATA_TYPE_FLOAT16, 2, pa, dims, strides, box, es,
               CU_TENSOR_MAP_INTERLEAVE_NONE, CU_TENSOR_MAP_SWIZZLE_128B,
               CU_TENSOR_MAP_L2_PROMOTION_L2_128B, CU_TENSOR_MAP_FLOAT_OOB_FILL_NONE);
    }
    {
        cuuint64_t dims[2] = {(cuuint64_t)D_DIM, (cuuint64_t)P};
        cuuint64_t strides[1] = {(cuuint64_t)D_DIM * 2};
        cuuint32_t box[2] = {KC, TN};
        cuuint32_t es[2] = {1, 1};
        encode(&tma_b, CU_TENSOR_MAP_DATA_TYPE_FLOAT16, 2, pb, dims, strides, box, es,
               CU_TENSOR_MAP_INTERLEAVE_NONE, CU_TENSOR_MAP_SWIZZLE_128B,
               CU_TENSOR_MAP_L2_PROMOTION_L2_128B, CU_TENSOR_MAP_FLOAT_OOB_FILL_NONE);
    }

    int dev = 0, sms = 148;
    cudaGetDevice(&dev);
    cudaDeviceGetAttribute(&sms, cudaDevAttrMultiProcessorCount, dev);

    // 1) normalize + fp16 convert + rowsum/counter/ticket zeroing
    int rows = N + P;
    conv_kernel<<<(rows * 32 + 255) / 256, 256>>>(emb, proto, N, P);

    // 2) persistent fused GEMM + softmax (ticket-scheduled tiles, free-running
    //    producer; last CTA of a stripe rescales it in place)
    cudaFuncSetAttribute(gemm_kernel, cudaFuncAttributeMaxDynamicSharedMemorySize, SMEM_TOTAL);
    gemm_kernel<<<sms * 2, 288, SMEM_TOTAL>>>(tma_a, tma_b, temp, out, N, P);
}

// round 14
// speedup vs baseline: 2.0017x; 1.1485x over previous
#include <cuda_runtime.h>
#include <cuda.h>
#include <cuda_fp16.h>
#include <cstdint>
#include <math.h>

// q[n][p] = softmax_p( <emb_n/|emb_n|, c_p/|c_p|> / T ), no max-subtraction.
// Round 14: exact R8 structure (one CTA per 128x128 tile, 8 consumer warps of
// 32x64, f32-acc HMMA, PIPE=3, 2 CTAs/SM, last-CTA-of-stripe rescale) +
// software double-buffering of B fragments across k16 steps: asm volatile
// ordering otherwise re-exposes LDSM latency before every 16-MMA block.
// Regs: 96 - 16 + 32 = ~112, at the 2-CTA cap (113) without spilling.

#define D_DIM 768
#define TM 128
#define TN 128
#define KC 64                        // K halves per chunk (128B rows, SW128)
#define NCH (D_DIM / KC)             // 12
#define PIPE 3
#define A_ST (TM * KC * 2)           // 16384 B
#define B_ST (TN * KC * 2)           // 16384 B
#define SMEM_A_OFF 1024
#define SMEM_B_OFF (SMEM_A_OFF + PIPE * A_ST)
#define SMEM_TOTAL (SMEM_B_OFF + PIPE * B_ST)   // 99328 B -> 2 CTAs/SM

#define OFF_FULL  0                  // 3 x 8B
#define OFF_EMPTY 32                 // 3 x 8B
#define OFF_FLAG  64                 // 4B
#define OFF_SINV  128                // 128 x 4B

#define MAXN 65536
#define MAXP 4096
#define MAXSTRIPES (MAXN / TM)
__device__ __half g_a16[(size_t)MAXN * D_DIM];   // normalized emb, fp16
__device__ __half g_b16[(size_t)MAXP * D_DIM];   // normalized prototypes, fp16
__device__ float g_rowsum[MAXN];
__device__ int g_cnt[MAXSTRIPES];

// ---------------------------------------------------------------------------
// PTX helpers
// ---------------------------------------------------------------------------
__device__ __forceinline__ uint32_t smem_u32(const void* p) {
    uint32_t a;
    asm("{ .reg .u64 t; cvta.to.shared.u64 t, %1; cvt.u32.u64 %0, t; }" : "=r"(a) : "l"(p));
    return a;
}
__device__ __forceinline__ void mbar_init(uint32_t bar, uint32_t cnt) {
    asm volatile("mbarrier.init.shared.b64 [%0], %1;" :: "r"(bar), "r"(cnt) : "memory");
}
__device__ __forceinline__ void mbar_expect_tx(uint32_t bar, uint32_t bytes) {
    asm volatile("mbarrier.arrive.expect_tx.shared.b64 _, [%0], %1;" :: "r"(bar), "r"(bytes) : "memory");
}
__device__ __forceinline__ void mbar_arrive(uint32_t bar) {
    asm volatile("mbarrier.arrive.shared.b64 _, [%0];" :: "r"(bar) : "memory");
}
__device__ __forceinline__ void mbar_wait(uint32_t bar, uint32_t parity) {
    uint32_t done;
    asm volatile(
        "{ .reg .pred p; mbarrier.try_wait.parity.acquire.cta.shared::cta.b64 p, [%1], %2;"
        " selp.b32 %0, 1, 0, p; }" : "=r"(done) : "r"(bar), "r"(parity) : "memory");
    if (!done) {
        asm volatile(
            "{ .reg .pred P1; WL%=:"
            " mbarrier.try_wait.parity.acquire.cta.shared::cta.b64 P1, [%0], %1, 0x989680;"
            " @P1 bra.uni WD%=; bra.uni WL%=; WD%=: }"
            :: "r"(bar), "r"(parity) : "memory");
    }
}
__device__ __forceinline__ void tma2d(uint32_t dst, const void* map, int x, int y, uint32_t bar) {
    asm volatile(
        "cp.async.bulk.tensor.2d.shared::cta.global.tile.mbarrier::complete_tx::bytes "
        "[%0], [%1, {%2, %3}], [%4];"
        :: "r"(dst), "l"(map), "r"(x), "r"(y), "r"(bar) : "memory");
}
__device__ __forceinline__ void ldsm4(uint32_t* r, uint32_t addr) {
    asm volatile("ldmatrix.sync.aligned.m8n8.x4.shared.b16 {%0,%1,%2,%3}, [%4];"
                 : "=r"(r[0]), "=r"(r[1]), "=r"(r[2]), "=r"(r[3]) : "r"(addr));
}
__device__ __forceinline__ void mma_f16(float* d, const uint32_t* a, uint32_t b0, uint32_t b1) {
    asm volatile(
        "mma.sync.aligned.m16n8k16.row.col.f32.f16.f16.f32 "
        "{%0,%1,%2,%3}, {%4,%5,%6,%7}, {%8,%9}, {%0,%1,%2,%3};"
        : "+f"(d[0]), "+f"(d[1]), "+f"(d[2]), "+f"(d[3])
        : "r"(a[0]), "r"(a[1]), "r"(a[2]), "r"(a[3]), "r"(b0), "r"(b1));
}
__device__ __forceinline__ float ex2(float x) {
    float y;
    asm("ex2.approx.ftz.f32 %0, %1;" : "=f"(y) : "f"(x));
    return y;
}
__device__ __forceinline__ void barc() {   // consumer-only named barrier (256 thr)
    asm volatile("bar.sync 1, 256;" ::: "memory");
}

// ---------------------------------------------------------------------------
// Kernel 1: warp-per-row: fp32 L2 norm -> normalized fp16 row.
// Also zeroes g_rowsum and g_cnt.
// ---------------------------------------------------------------------------
__global__ void conv_kernel(const float* __restrict__ A, const float* __restrict__ B,
                            int N, int P) {
    int gtid = blockIdx.x * blockDim.x + threadIdx.x;
    if (gtid < MAXSTRIPES) g_cnt[gtid] = 0;
    int w = gtid >> 5;
    int lane = threadIdx.x & 31;
    if (w >= N + P) return;
    const float4* src;
    __half2* dst;
    if (w < N) {
        src = (const float4*)(A + (size_t)w * D_DIM);
        dst = (__half2*)(g_a16 + (size_t)w * D_DIM);
        if (lane == 0) g_rowsum[w] = 0.0f;
    } else {
        int r = w - N;
        src = (const float4*)(B + (size_t)r * D_DIM);
        dst = (__half2*)(g_b16 + (size_t)r * D_DIM);
    }
    float4 v[D_DIM / 128];
    float ss = 0.0f;
#pragma unroll
    for (int i = 0; i < D_DIM / 128; i++) {
        v[i] = src[lane + 32 * i];
        ss += v[i].x * v[i].x + v[i].y * v[i].y + v[i].z * v[i].z + v[i].w * v[i].w;
    }
#pragma unroll
    for (int o = 16; o; o >>= 1) ss += __shfl_xor_sync(0xffffffffu, ss, o);
    float inv = 1.0f / fmaxf(sqrtf(ss), 1e-12f);
#pragma unroll
    for (int i = 0; i < D_DIM / 128; i++) {
        dst[(lane + 32 * i) * 2]     = __floats2half2_rn(v[i].x * inv, v[i].y * inv);
        dst[(lane + 32 * i) * 2 + 1] = __floats2half2_rn(v[i].z * inv, v[i].w * inv);
    }
}

// ---------------------------------------------------------------------------
// Kernel 2: one CTA per 128x128 tile. 8 consumer warps (32x64) + TMA producer.
// B fragments double-buffered across k16 steps.
// ---------------------------------------------------------------------------
__global__ void __launch_bounds__(288, 2)
gemm_kernel(const __grid_constant__ CUtensorMap tmap_a,
            const __grid_constant__ CUtensorMap tmap_b,
            const float* __restrict__ tptr,
            float* __restrict__ out,
            int N, int P) {
    extern __shared__ char smem[];
    uint32_t sbase = smem_u32(smem);
    const int tid = threadIdx.x, wid = tid >> 5, lane = tid & 31;
    const int ntp = P / TN;
    const int stripe = blockIdx.x / ntp;
    const int n0 = stripe * TM;
    const int p0 = (blockIdx.x % ntp) * TN;
    int* sflag = (int*)(smem + OFF_FLAG);
    float* sinv = (float*)(smem + OFF_SINV);

    if (tid == 0) {
#pragma unroll
        for (int s = 0; s < PIPE; s++) {
            mbar_init(sbase + OFF_FULL + s * 8, 1);
            mbar_init(sbase + OFF_EMPTY + s * 8, 8);
        }
    }
    __syncthreads();
    asm volatile("fence.proxy.async.shared::cta;" ::: "memory");

    if (wid == 8) {
        if (lane == 0) {
            int st = 0, ph = 1;
            for (int c = 0; c < NCH; c++) {
                mbar_wait(sbase + OFF_EMPTY + st * 8, ph);
                mbar_expect_tx(sbase + OFF_FULL + st * 8, A_ST + B_ST);
                tma2d(sbase + SMEM_A_OFF + st * A_ST, &tmap_a, c * KC, n0,
                      sbase + OFF_FULL + st * 8);
                tma2d(sbase + SMEM_B_OFF + st * B_ST, &tmap_b, c * KC, p0,
                      sbase + OFF_FULL + st * 8);
                if (++st == PIPE) { st = 0; ph ^= 1; }
            }
        }
        return;
    }

    // consumers: warp (wm, wn) owns 32x64 subtile
    const int wm = wid >> 1;
    const int wn = wid & 1;
    const int lrow = lane & 15;
    const uint32_t lgrp = (uint32_t)((lane >> 4) * 16);
    const uint32_t kb0 = (uint32_t)((wid & 3) * 32);   // staggered k16 start

    uint32_t arow[2], asw[2], brow[4], bsw[4];
#pragma unroll
    for (int mt = 0; mt < 2; mt++) {
        uint32_t r = (uint32_t)(wm * 32 + mt * 16 + lrow);
        arow[mt] = r * 128;
        asw[mt] = (r & 7) << 4;
    }
#pragma unroll
    for (int bt = 0; bt < 4; bt++) {
        uint32_t r = (uint32_t)(wn * 64 + bt * 16 + lrow);
        brow[bt] = r * 128;
        bsw[bt] = (r & 7) << 4;
    }

    float acc[2][8][4];
#pragma unroll
    for (int mt = 0; mt < 2; mt++)
#pragma unroll
        for (int nt = 0; nt < 8; nt++)
#pragma unroll
            for (int q = 0; q < 4; q++) acc[mt][nt][q] = 0.0f;

#pragma unroll
    for (int c = 0; c < NCH; c++) {
        const int st = c % PIPE;                 // compile-time
        const uint32_t wph = (c / PIPE) & 1;     // compile-time
        mbar_wait(sbase + OFF_FULL + st * 8, wph);
        const uint32_t abase = sbase + SMEM_A_OFF + st * A_ST;
        const uint32_t bbase = sbase + SMEM_B_OFF + st * B_ST;

        // B fragments double-buffered across ks
        uint32_t bf[2][4][4];
        {
            const uint32_t kin0 = (kb0 & 96) | lgrp;
#pragma unroll
            for (int bt = 0; bt < 4; bt++)
                ldsm4(bf[0][bt], bbase + brow[bt] + (kin0 ^ bsw[bt]));
        }
#pragma unroll
        for (int ks = 0; ks < 4; ks++) {
            const int cur = ks & 1, nxt = cur ^ 1;
            const uint32_t kin = ((kb0 + ks * 32) & 96) | lgrp;
            uint32_t a[2][4];
#pragma unroll
            for (int mt = 0; mt < 2; mt++)
                ldsm4(a[mt], abase + arow[mt] + (kin ^ asw[mt]));
            if (ks < 3) {
                const uint32_t kin_n = ((kb0 + (ks + 1) * 32) & 96) | lgrp;
#pragma unroll
                for (int bt = 0; bt < 4; bt++)
                    ldsm4(bf[nxt][bt], bbase + brow[bt] + (kin_n ^ bsw[bt]));
            } else if (lane == 0) {
                mbar_arrive(sbase + OFF_EMPTY + st * 8);
            }
#pragma unroll
            for (int mt = 0; mt < 2; mt++)
#pragma unroll
                for (int nt = 0; nt < 8; nt++)
                    mma_f16(acc[mt][nt], a[mt],
                            bf[cur][nt >> 1][nt & 1], bf[cur][nt >> 1][2 + (nt & 1)]);
        }
    }

    // epilogue: e = exp2(acc * log2(e)/T) -> out; rowsum atomics
    const float s = 1.4426950408889634f / tptr[0];
    const int qrow = lane >> 2;
    const int qc = 2 * (lane & 3);
#pragma unroll
    for (int mt = 0; mt < 2; mt++) {
#pragma unroll
        for (int h = 0; h < 2; h++) {
            int row = n0 + wm * 32 + mt * 16 + h * 8 + qrow;
            float rs = 0.0f;
            float* orow = out + (size_t)row * P + p0 + wn * 64 + qc;
#pragma unroll
            for (int nt = 0; nt < 8; nt++) {
                float e0 = ex2(acc[mt][nt][2 * h] * s);
                float e1 = ex2(acc[mt][nt][2 * h + 1] * s);
                rs += e0 + e1;
                *(float2*)(orow + nt * 8) = make_float2(e0, e1);
            }
            rs += __shfl_xor_sync(0xffffffffu, rs, 1);
            rs += __shfl_xor_sync(0xffffffffu, rs, 2);
            if ((lane & 3) == 0) atomicAdd(&g_rowsum[row], rs);
        }
    }

    // ---- last-CTA-of-stripe scales the stripe in place ----
    __threadfence();
    barc();
    if (tid == 0) {
        int old = atomicAdd(&g_cnt[stripe], 1);
        sflag[0] = (old == ntp - 1);
    }
    barc();
    if (sflag[0]) {
        if (tid < TM) sinv[tid] = 1.0f / g_rowsum[n0 + tid];
        barc();
        const int p4 = P >> 2;
        float4* base = (float4*)(out + (size_t)n0 * P);
        for (int r = 0; r < TM; r++) {
            float inv = sinv[r];
            float4* rowp = base + r * p4;
#pragma unroll 2
            for (int c4 = tid; c4 < p4; c4 += 256) {
                float4 v = rowp[c4];
                v.x *= inv; v.y *= inv; v.z *= inv; v.w *= inv;
                rowp[c4] = v;
            }
        }
    }
}

// ---------------------------------------------------------------------------
extern "C" void kernel_launch(void* const* d_in, const int* in_sizes, int n_in,
                              void* d_out, int out_size) {
    const float* emb = (const float*)d_in[0];
    const float* proto = (const float*)d_in[1];
    const float* temp = (const float*)d_in[2];
    float* out = (float*)d_out;
    const int N = in_sizes[0] / D_DIM;
    const int P = in_sizes[1] / D_DIM;

    typedef CUresult (*EncodeFn)(CUtensorMap*, CUtensorMapDataType, cuuint32_t, void*,
                                 const cuuint64_t*, const cuuint64_t*, const cuuint32_t*,
                                 const cuuint32_t*, CUtensorMapInterleave, CUtensorMapSwizzle,
                                 CUtensorMapL2promotion, CUtensorMapFloatOOBfill);
    EncodeFn encode = nullptr;
    cudaDriverEntryPointQueryResult qr;
    cudaGetDriverEntryPoint("cuTensorMapEncodeTiled", (void**)&encode,
                            cudaEnableDefault, &qr);

    void *pa = nullptr, *pb = nullptr;
    cudaGetSymbolAddress(&pa, g_a16);
    cudaGetSymbolAddress(&pb, g_b16);

    CUtensorMap tma_a{}, tma_b{};
    {
        cuuint64_t dims[2] = {(cuuint64_t)D_DIM, (cuuint64_t)N};
        cuuint64_t strides[1] = {(cuuint64_t)D_DIM * 2};
        cuuint32_t box[2] = {KC, TM};
        cuuint32_t es[2] = {1, 1};
        encode(&tma_a, CU_TENSOR_MAP_DATA_TYPE_FLOAT16, 2, pa, dims, strides, box, es,
               CU_TENSOR_MAP_INTERLEAVE_NONE, CU_TENSOR_MAP_SWIZZLE_128B,
               CU_TENSOR_MAP_L2_PROMOTION_L2_128B, CU_TENSOR_MAP_FLOAT_OOB_FILL_NONE);
    }
    {
        cuuint64_t dims[2] = {(cuuint64_t)D_DIM, (cuuint64_t)P};
        cuuint64_t strides[1] = {(cuuint64_t)D_DIM * 2};
        cuuint32_t box[2] = {KC, TN};
        cuuint32_t es[2] = {1, 1};
        encode(&tma_b, CU_TENSOR_MAP_DATA_TYPE_FLOAT16, 2, pb, dims, strides, box, es,
               CU_TENSOR_MAP_INTERLEAVE_NONE, CU_TENSOR_MAP_SWIZZLE_128B,
               CU_TENSOR_MAP_L2_PROMOTION_L2_128B, CU_TENSOR_MAP_FLOAT_OOB_FILL_NONE);
    }

    // 1) normalize + fp16 convert + rowsum/counter zeroing
    int rows = N + P;
    conv_kernel<<<(rows * 32 + 255) / 256, 256>>>(emb, proto, N, P);

    // 2) fused GEMM + softmax (p fastest -> A-tile L2 sharing; last CTA of a
    //    stripe rescales it in place)
    int NT = (N / TM) * (P / TN);
    cudaFuncSetAttribute(gemm_kernel, cudaFuncAttributeMaxDynamicSharedMemorySize, SMEM_TOTAL);
    gemm_kernel<<<NT, 288, SMEM_TOTAL>>>(tma_a, tma_b, temp, out, N, P);
}

// round 16
// speedup vs baseline: 2.0036x; 1.0010x over previous
#include <cuda_runtime.h>
#include <cuda.h>
#include <cuda_fp16.h>
#include <cstdint>
#include <math.h>

// q[n][p] = softmax_p( <emb_n/|emb_n|, c_p/|c_p|> / T ), no max-subtraction.
// Round 16: revert R15's cross-stage pre-acquire (failed accuracy gate at
// 1.0e-3 — suspected low-incidence race). Base = R14 (proven 1310us,
// rel_err 1.06e-4) + A-fragment double-buffering: prefetch a[ks+1] during
// ks's MMA block. All stage-st smem reads now complete by end of ks==2, so
// the EMPTY arrive at ks==3 has NO smem reads after it (strictly safer
// ordering than R14). Regs ~104 < 113 cap (2 CTAs/SM).

#define D_DIM 768
#define TM 128
#define TN 128
#define KC 64                        // K halves per chunk (128B rows, SW128)
#define NCH (D_DIM / KC)             // 12
#define PIPE 3
#define A_ST (TM * KC * 2)           // 16384 B
#define B_ST (TN * KC * 2)           // 16384 B
#define SMEM_A_OFF 1024
#define SMEM_B_OFF (SMEM_A_OFF + PIPE * A_ST)
#define SMEM_TOTAL (SMEM_B_OFF + PIPE * B_ST)   // 99328 B -> 2 CTAs/SM

#define OFF_FULL  0                  // 3 x 8B
#define OFF_EMPTY 32                 // 3 x 8B
#define OFF_FLAG  64                 // 4B
#define OFF_SINV  128                // 128 x 4B

#define MAXN 65536
#define MAXP 4096
#define MAXSTRIPES (MAXN / TM)
__device__ __half g_a16[(size_t)MAXN * D_DIM];   // normalized emb, fp16
__device__ __half g_b16[(size_t)MAXP * D_DIM];   // normalized prototypes, fp16
__device__ float g_rowsum[MAXN];
__device__ int g_cnt[MAXSTRIPES];

// ---------------------------------------------------------------------------
// PTX helpers
// ---------------------------------------------------------------------------
__device__ __forceinline__ uint32_t smem_u32(const void* p) {
    uint32_t a;
    asm("{ .reg .u64 t; cvta.to.shared.u64 t, %1; cvt.u32.u64 %0, t; }" : "=r"(a) : "l"(p));
    return a;
}
__device__ __forceinline__ void mbar_init(uint32_t bar, uint32_t cnt) {
    asm volatile("mbarrier.init.shared.b64 [%0], %1;" :: "r"(bar), "r"(cnt) : "memory");
}
__device__ __forceinline__ void mbar_expect_tx(uint32_t bar, uint32_t bytes) {
    asm volatile("mbarrier.arrive.expect_tx.shared.b64 _, [%0], %1;" :: "r"(bar), "r"(bytes) : "memory");
}
__device__ __forceinline__ void mbar_arrive(uint32_t bar) {
    asm volatile("mbarrier.arrive.shared.b64 _, [%0];" :: "r"(bar) : "memory");
}
__device__ __forceinline__ void mbar_wait(uint32_t bar, uint32_t parity) {
    uint32_t done;
    asm volatile(
        "{ .reg .pred p; mbarrier.try_wait.parity.acquire.cta.shared::cta.b64 p, [%1], %2;"
        " selp.b32 %0, 1, 0, p; }" : "=r"(done) : "r"(bar), "r"(parity) : "memory");
    if (!done) {
        asm volatile(
            "{ .reg .pred P1; WL%=:"
            " mbarrier.try_wait.parity.acquire.cta.shared::cta.b64 P1, [%0], %1, 0x989680;"
            " @P1 bra.uni WD%=; bra.uni WL%=; WD%=: }"
            :: "r"(bar), "r"(parity) : "memory");
    }
}
__device__ __forceinline__ void tma2d(uint32_t dst, const void* map, int x, int y, uint32_t bar) {
    asm volatile(
        "cp.async.bulk.tensor.2d.shared::cta.global.tile.mbarrier::complete_tx::bytes "
        "[%0], [%1, {%2, %3}], [%4];"
        :: "r"(dst), "l"(map), "r"(x), "r"(y), "r"(bar) : "memory");
}
__device__ __forceinline__ void ldsm4(uint32_t* r, uint32_t addr) {
    asm volatile("ldmatrix.sync.aligned.m8n8.x4.shared.b16 {%0,%1,%2,%3}, [%4];"
                 : "=r"(r[0]), "=r"(r[1]), "=r"(r[2]), "=r"(r[3]) : "r"(addr));
}
__device__ __forceinline__ void mma_f16(float* d, const uint32_t* a, uint32_t b0, uint32_t b1) {
    asm volatile(
        "mma.sync.aligned.m16n8k16.row.col.f32.f16.f16.f32 "
        "{%0,%1,%2,%3}, {%4,%5,%6,%7}, {%8,%9}, {%0,%1,%2,%3};"
        : "+f"(d[0]), "+f"(d[1]), "+f"(d[2]), "+f"(d[3])
        : "r"(a[0]), "r"(a[1]), "r"(a[2]), "r"(a[3]), "r"(b0), "r"(b1));
}
__device__ __forceinline__ float ex2(float x) {
    float y;
    asm("ex2.approx.ftz.f32 %0, %1;" : "=f"(y) : "f"(x));
    return y;
}
__device__ __forceinline__ void barc() {   // consumer-only named barrier (256 thr)
    asm volatile("bar.sync 1, 256;" ::: "memory");
}

// ---------------------------------------------------------------------------
// Kernel 1: warp-per-row: fp32 L2 norm -> normalized fp16 row.
// Also zeroes g_rowsum and g_cnt.
// ---------------------------------------------------------------------------
__global__ void conv_kernel(const float* __restrict__ A, const float* __restrict__ B,
                            int N, int P) {
    int gtid = blockIdx.x * blockDim.x + threadIdx.x;
    if (gtid < MAXSTRIPES) g_cnt[gtid] = 0;
    int w = gtid >> 5;
    int lane = threadIdx.x & 31;
    if (w >= N + P) return;
    const float4* src;
    __half2* dst;
    if (w < N) {
        src = (const float4*)(A + (size_t)w * D_DIM);
        dst = (__half2*)(g_a16 + (size_t)w * D_DIM);
        if (lane == 0) g_rowsum[w] = 0.0f;
    } else {
        int r = w - N;
        src = (const float4*)(B + (size_t)r * D_DIM);
        dst = (__half2*)(g_b16 + (size_t)r * D_DIM);
    }
    float4 v[D_DIM / 128];
    float ss = 0.0f;
#pragma unroll
    for (int i = 0; i < D_DIM / 128; i++) {
        v[i] = src[lane + 32 * i];
        ss += v[i].x * v[i].x + v[i].y * v[i].y + v[i].z * v[i].z + v[i].w * v[i].w;
    }
#pragma unroll
    for (int o = 16; o; o >>= 1) ss += __shfl_xor_sync(0xffffffffu, ss, o);
    float inv = 1.0f / fmaxf(sqrtf(ss), 1e-12f);
#pragma unroll
    for (int i = 0; i < D_DIM / 128; i++) {
        dst[(lane + 32 * i) * 2]     = __floats2half2_rn(v[i].x * inv, v[i].y * inv);
        dst[(lane + 32 * i) * 2 + 1] = __floats2half2_rn(v[i].z * inv, v[i].w * inv);
    }
}

// ---------------------------------------------------------------------------
// Kernel 2: one CTA per 128x128 tile. 8 consumer warps (32x64) + TMA producer.
// A and B fragments both double-buffered across k16 steps (within one stage).
// ---------------------------------------------------------------------------
__global__ void __launch_bounds__(288, 2)
gemm_kernel(const __grid_constant__ CUtensorMap tmap_a,
            const __grid_constant__ CUtensorMap tmap_b,
            const float* __restrict__ tptr,
            float* __restrict__ out,
            int N, int P) {
    extern __shared__ char smem[];
    uint32_t sbase = smem_u32(smem);
    const int tid = threadIdx.x, wid = tid >> 5, lane = tid & 31;
    const int ntp = P / TN;
    const int stripe = blockIdx.x / ntp;
    const int n0 = stripe * TM;
    const int p0 = (blockIdx.x % ntp) * TN;
    int* sflag = (int*)(smem + OFF_FLAG);
    float* sinv = (float*)(smem + OFF_SINV);

    if (tid == 0) {
#pragma unroll
        for (int s = 0; s < PIPE; s++) {
            mbar_init(sbase + OFF_FULL + s * 8, 1);
            mbar_init(sbase + OFF_EMPTY + s * 8, 8);
        }
    }
    __syncthreads();
    asm volatile("fence.proxy.async.shared::cta;" ::: "memory");

    if (wid == 8) {
        if (lane == 0) {
            int st = 0, ph = 1;
            for (int c = 0; c < NCH; c++) {
                mbar_wait(sbase + OFF_EMPTY + st * 8, ph);
                mbar_expect_tx(sbase + OFF_FULL + st * 8, A_ST + B_ST);
                tma2d(sbase + SMEM_A_OFF + st * A_ST, &tmap_a, c * KC, n0,
                      sbase + OFF_FULL + st * 8);
                tma2d(sbase + SMEM_B_OFF + st * B_ST, &tmap_b, c * KC, p0,
                      sbase + OFF_FULL + st * 8);
                if (++st == PIPE) { st = 0; ph ^= 1; }
            }
        }
        return;
    }

    // consumers: warp (wm, wn) owns 32x64 subtile
    const int wm = wid >> 1;
    const int wn = wid & 1;
    const int lrow = lane & 15;
    const uint32_t lgrp = (uint32_t)((lane >> 4) * 16);
    const uint32_t kb0 = (uint32_t)((wid & 3) * 32);   // staggered k16 start

    uint32_t arow[2], asw[2], brow[4], bsw[4];
#pragma unroll
    for (int mt = 0; mt < 2; mt++) {
        uint32_t r = (uint32_t)(wm * 32 + mt * 16 + lrow);
        arow[mt] = r * 128;
        asw[mt] = (r & 7) << 4;
    }
#pragma unroll
    for (int bt = 0; bt < 4; bt++) {
        uint32_t r = (uint32_t)(wn * 64 + bt * 16 + lrow);
        brow[bt] = r * 128;
        bsw[bt] = (r & 7) << 4;
    }

    float acc[2][8][4];
#pragma unroll
    for (int mt = 0; mt < 2; mt++)
#pragma unroll
        for (int nt = 0; nt < 8; nt++)
#pragma unroll
            for (int q = 0; q < 4; q++) acc[mt][nt][q] = 0.0f;

#pragma unroll
    for (int c = 0; c < NCH; c++) {
        const int st = c % PIPE;                 // compile-time
        const uint32_t wph = (c / PIPE) & 1;     // compile-time
        mbar_wait(sbase + OFF_FULL + st * 8, wph);
        const uint32_t abase = sbase + SMEM_A_OFF + st * A_ST;
        const uint32_t bbase = sbase + SMEM_B_OFF + st * B_ST;

        // A and B fragments double-buffered across ks (within this stage)
        uint32_t af[2][2][4];
        uint32_t bf[2][4][4];
        {
            const uint32_t kin0 = (kb0 & 96) | lgrp;
#pragma unroll
            for (int mt = 0; mt < 2; mt++)
                ldsm4(af[0][mt], abase + arow[mt] + (kin0 ^ asw[mt]));
#pragma unroll
            for (int bt = 0; bt < 4; bt++)
                ldsm4(bf[0][bt], bbase + brow[bt] + (kin0 ^ bsw[bt]));
        }
#pragma unroll
        for (int ks = 0; ks < 4; ks++) {
            const int cur = ks & 1, nxt = cur ^ 1;
            if (ks < 3) {
                const uint32_t kin_n = ((kb0 + (ks + 1) * 32) & 96) | lgrp;
#pragma unroll
                for (int mt = 0; mt < 2; mt++)
                    ldsm4(af[nxt][mt], abase + arow[mt] + (kin_n ^ asw[mt]));
#pragma unroll
                for (int bt = 0; bt < 4; bt++)
                    ldsm4(bf[nxt][bt], bbase + brow[bt] + (kin_n ^ bsw[bt]));
            } else if (lane == 0) {
                // all stage-st smem reads finished at end of ks==2
                mbar_arrive(sbase + OFF_EMPTY + st * 8);
            }
#pragma unroll
            for (int mt = 0; mt < 2; mt++)
#pragma unroll
                for (int nt = 0; nt < 8; nt++)
                    mma_f16(acc[mt][nt], af[cur][mt],
                            bf[cur][nt >> 1][nt & 1], bf[cur][nt >> 1][2 + (nt & 1)]);
        }
    }

    // epilogue: e = exp2(acc * log2(e)/T) -> out; rowsum atomics
    const float s = 1.4426950408889634f / tptr[0];
    const int qrow = lane >> 2;
    const int qc = 2 * (lane & 3);
#pragma unroll
    for (int mt = 0; mt < 2; mt++) {
#pragma unroll
        for (int h = 0; h < 2; h++) {
            int row = n0 + wm * 32 + mt * 16 + h * 8 + qrow;
            float rs = 0.0f;
            float* orow = out + (size_t)row * P + p0 + wn * 64 + qc;
#pragma unroll
            for (int nt = 0; nt < 8; nt++) {
                float e0 = ex2(acc[mt][nt][2 * h] * s);
                float e1 = ex2(acc[mt][nt][2 * h + 1] * s);
                rs += e0 + e1;
                *(float2*)(orow + nt * 8) = make_float2(e0, e1);
            }
            rs += __shfl_xor_sync(0xffffffffu, rs, 1);
            rs += __shfl_xor_sync(0xffffffffu, rs, 2);
            if ((lane & 3) == 0) atomicAdd(&g_rowsum[row], rs);
        }
    }

    // ---- last-CTA-of-stripe scales the stripe in place ----
    __threadfence();
    barc();
    if (tid == 0) {
        int old = atomicAdd(&g_cnt[stripe], 1);
        sflag[0] = (old == ntp - 1);
    }
    barc();
    if (sflag[0]) {
        if (tid < TM) sinv[tid] = 1.0f / g_rowsum[n0 + tid];
        barc();
        const int p4 = P >> 2;
        float4* base = (float4*)(out + (size_t)n0 * P);
        for (int r = 0; r < TM; r++) {
            float inv = sinv[r];
            float4* rowp = base + r * p4;
#pragma unroll 2
            for (int c4 = tid; c4 < p4; c4 += 256) {
                float4 v = rowp[c4];
                v.x *= inv; v.y *= inv; v.z *= inv; v.w *= inv;
                rowp[c4] = v;
            }
        }
    }
}

// ---------------------------------------------------------------------------
extern "C" void kernel_launch(void* const* d_in, const int* in_sizes, int n_in,
                              void* d_out, int out_size) {
    const float* emb = (const float*)d_in[0];
    const float* proto = (const float*)d_in[1];
    const float* temp = (const float*)d_in[2];
    float* out = (float*)d_out;
    const int N = in_sizes[0] / D_DIM;
    const int P = in_sizes[1] / D_DIM;

    typedef CUresult (*EncodeFn)(CUtensorMap*, CUtensorMapDataType, cuuint32_t, void*,
                                 const cuuint64_t*, const cuuint64_t*, const cuuint32_t*,
                                 const cuuint32_t*, CUtensorMapInterleave, CUtensorMapSwizzle,
                                 CUtensorMapL2promotion, CUtensorMapFloatOOBfill);
    EncodeFn encode = nullptr;
    cudaDriverEntryPointQueryResult qr;
    cudaGetDriverEntryPoint("cuTensorMapEncodeTiled", (void**)&encode,
                            cudaEnableDefault, &qr);

    void *pa = nullptr, *pb = nullptr;
    cudaGetSymbolAddress(&pa, g_a16);
    cudaGetSymbolAddress(&pb, g_b16);

    CUtensorMap tma_a{}, tma_b{};
    {
        cuuint64_t dims[2] = {(cuuint64_t)D_DIM, (cuuint64_t)N};
        cuuint64_t strides[1] = {(cuuint64_t)D_DIM * 2};
        cuuint32_t box[2] = {KC, TM};
        cuuint32_t es[2] = {1, 1};
        encode(&tma_a, CU_TENSOR_MAP_DATA_TYPE_FLOAT16, 2, pa, dims, strides, box, es,
               CU_TENSOR_MAP_INTERLEAVE_NONE, CU_TENSOR_MAP_SWIZZLE_128B,
               CU_TENSOR_MAP_L2_PROMOTION_L2_128B, CU_TENSOR_MAP_FLOAT_OOB_FILL_NONE);
    }
    {
        cuuint64_t dims[2] = {(cuuint64_t)D_DIM, (cuuint64_t)P};
        cuuint64_t strides[1] = {(cuuint64_t)D_DIM * 2};
        cuuint32_t box[2] = {KC, TN};
        cuuint32_t es[2] = {1, 1};
        encode(&tma_b, CU_TENSOR_MAP_DATA_TYPE_FLOAT16, 2, pb, dims, strides, box, es,
               CU_TENSOR_MAP_INTERLEAVE_NONE, CU_TENSOR_MAP_SWIZZLE_128B,
               CU_TENSOR_MAP_L2_PROMOTION_L2_128B, CU_TENSOR_MAP_FLOAT_OOB_FILL_NONE);
    }

    // 1) normalize + fp16 convert + rowsum/counter zeroing
    int rows = N + P;
    conv_kernel<<<(rows * 32 + 255) / 256, 256>>>(emb, proto, N, P);

    // 2) fused GEMM + softmax (p fastest -> A-tile L2 sharing; last CTA of a
    //    stripe rescales it in place)
    int NT = (N / TM) * (P / TN);
    cudaFuncSetAttribute(gemm_kernel, cudaFuncAttributeMaxDynamicSharedMemorySize, SMEM_TOTAL);
    gemm_kernel<<<NT, 288, SMEM_TOTAL>>>(tma_a, tma_b, temp, out, N, P);
}